// round 2
// baseline (speedup 1.0000x reference)
#include <cuda_runtime.h>
#include <cstdint>

#define NN 50000
#define NE 800000
#define NG 64
#define HID 300
#define HID2 600
#define NLAYER 5
#define EPSV 1e-5f

// ---------------- scratch (static __device__, no allocs) ----------------
__device__ float g_hraw[(size_t)NN * HID];    // pre-BN node features (GEMM2 out / lin0 out)
__device__ float g_agg [(size_t)NN * HID];    // aggregated messages
__device__ float g_t   [(size_t)NN * HID2];   // pre-BN hidden (GEMM1 out)
__device__ int   g_deg [NN];
__device__ int   g_rowptr[NN + 1];
__device__ int   g_cursor[NN];
__device__ int   g_srcs[NE];
__device__ float g_ews [NE];
__device__ float g_sum1[HID2], g_sq1[HID2], g_a1[HID2], g_c1[HID2];
__device__ float g_sum2[HID],  g_sq2[HID],  g_a2[HID],  g_c2[HID];

// ---------------- small utility kernels ----------------
__global__ void k_zero_f(float* p, int n) {
    int i = blockIdx.x * blockDim.x + threadIdx.x;
    if (i < n) p[i] = 0.f;
}
__global__ void k_zero_deg() {
    int i = blockIdx.x * blockDim.x + threadIdx.x;
    if (i < NN) g_deg[i] = 0;
}
__global__ void k_count(const int* __restrict__ dst) {
    int e = blockIdx.x * blockDim.x + threadIdx.x;
    if (e < NE) atomicAdd(&g_deg[dst[e]], 1);
}
// single-block exclusive scan of g_deg -> g_rowptr, g_cursor
__global__ void k_scan() {
    __shared__ int sh[1024];
    int offset = 0;
    for (int base = 0; base < NN; base += 1024) {
        int i = base + threadIdx.x;
        int v = (i < NN) ? g_deg[i] : 0;
        sh[threadIdx.x] = v;
        __syncthreads();
        #pragma unroll
        for (int d = 1; d < 1024; d <<= 1) {
            int t = (threadIdx.x >= d) ? sh[threadIdx.x - d] : 0;
            __syncthreads();
            sh[threadIdx.x] += t;
            __syncthreads();
        }
        int incl = sh[threadIdx.x];
        if (i < NN) {
            int excl = offset + incl - v;
            g_rowptr[i] = excl;
            g_cursor[i] = excl;
        }
        offset += sh[1023];
        __syncthreads();
    }
    if (threadIdx.x == 0) g_rowptr[NN] = offset;
}
__global__ void k_scatter(const int* __restrict__ src, const int* __restrict__ dst,
                          const float* __restrict__ ea) {
    int e = blockIdx.x * blockDim.x + threadIdx.x;
    if (e < NE) {
        int d = dst[e];
        int p = atomicAdd(&g_cursor[d], 1);
        g_srcs[p] = src[e];
        g_ews[p]  = ea[e];
    }
}

// ---------------- SpMM: agg[n] = sum_e ew * f(h[src]) ----------------
// TRANS: f(v) = relu(a[f]*v + c[f]); else f(v) = v
template <bool TRANS>
__global__ void k_spmm(const float* __restrict__ hraw,
                       const float* __restrict__ a, const float* __restrict__ c) {
    int n = blockIdx.x;
    int f = threadIdx.x;
    int beg = g_rowptr[n], end = g_rowptr[n + 1];
    if (f >= HID) return;
    float af = 0.f, cf = 0.f;
    if (TRANS) { af = a[f]; cf = c[f]; }
    float acc = 0.f;
    for (int e = beg; e < end; e++) {
        int s  = g_srcs[e];
        float w = g_ews[e];
        float v = __ldg(hraw + (size_t)s * HID + f);
        if (TRANS) v = fmaxf(fmaf(af, v, cf), 0.f);
        acc = fmaf(w, v, acc);
    }
    g_agg[(size_t)n * HID + f] = acc;
}

// ---------------- tiled fp32 GEMM: C = f(A) @ B + bias, fused BN-stats ----------------
// A: [M,K] row-major, B: [K,N] row-major. f applied element-wise on A by K-column:
// TRANS_A: f(v) = relu(ta[k]*v + tc[k]); else identity.
// STATS: atomically accumulate per-column sum / sumsq of C (rows < M only).
#define BM 128
#define BN 128
#define BK 8
#define TM 8
#define TN 8
template <bool TRANS_A, bool STATS>
__global__ __launch_bounds__(256, 2)
void k_gemm(const float* __restrict__ A, const float* __restrict__ B,
            const float* __restrict__ bias,
            const float* __restrict__ ta, const float* __restrict__ tc,
            float* __restrict__ C, int M, int N, int K,
            float* __restrict__ sum_out, float* __restrict__ sq_out) {
    __shared__ float As[BK][BM + 4];
    __shared__ float Bs[BK][BN];
    __shared__ float red[16][BN];

    int tid = threadIdx.x;
    int tx = tid & 15, ty = tid >> 4;
    int m0 = blockIdx.y * BM, n0 = blockIdx.x * BN;

    int arow = tid >> 1;          // 0..127
    int ak   = (tid & 1) * 4;     // 0 or 4
    int bk   = tid >> 5;          // 0..7
    int bn   = (tid & 31) * 4;    // 0..124

    float acc[TM][TN];
    #pragma unroll
    for (int i = 0; i < TM; i++)
        #pragma unroll
        for (int j = 0; j < TN; j++) acc[i][j] = 0.f;

    for (int k0 = 0; k0 < K; k0 += BK) {
        float4 av = make_float4(0.f, 0.f, 0.f, 0.f);
        if (m0 + arow < M && k0 + ak < K) {
            av = *(const float4*)(A + (size_t)(m0 + arow) * K + k0 + ak);
            if (TRANS_A) {
                float4 a4 = *(const float4*)(ta + k0 + ak);
                float4 c4 = *(const float4*)(tc + k0 + ak);
                av.x = fmaxf(fmaf(a4.x, av.x, c4.x), 0.f);
                av.y = fmaxf(fmaf(a4.y, av.y, c4.y), 0.f);
                av.z = fmaxf(fmaf(a4.z, av.z, c4.z), 0.f);
                av.w = fmaxf(fmaf(a4.w, av.w, c4.w), 0.f);
            }
        }
        As[ak + 0][arow] = av.x;
        As[ak + 1][arow] = av.y;
        As[ak + 2][arow] = av.z;
        As[ak + 3][arow] = av.w;

        float4 bv = make_float4(0.f, 0.f, 0.f, 0.f);
        if (k0 + bk < K && n0 + bn < N)
            bv = *(const float4*)(B + (size_t)(k0 + bk) * N + n0 + bn);
        *(float4*)&Bs[bk][bn] = bv;

        __syncthreads();
        #pragma unroll
        for (int kk = 0; kk < BK; kk++) {
            float a[TM], b[TN];
            #pragma unroll
            for (int i = 0; i < TM; i++) a[i] = As[kk][ty * TM + i];
            #pragma unroll
            for (int j = 0; j < TN; j++) b[j] = Bs[kk][tx * TN + j];
            #pragma unroll
            for (int i = 0; i < TM; i++)
                #pragma unroll
                for (int j = 0; j < TN; j++)
                    acc[i][j] = fmaf(a[i], b[j], acc[i][j]);
        }
        __syncthreads();
    }

    // bias
    float bv[TN];
    #pragma unroll
    for (int j = 0; j < TN; j++) {
        int col = n0 + tx * TN + j;
        bv[j] = (col < N) ? bias[col] : 0.f;
    }
    #pragma unroll
    for (int i = 0; i < TM; i++)
        #pragma unroll
        for (int j = 0; j < TN; j++) acc[i][j] += bv[j];

    // store
    #pragma unroll
    for (int i = 0; i < TM; i++) {
        int row = m0 + ty * TM + i;
        if (row < M) {
            int colb = n0 + tx * TN;
            if (colb < N)
                *(float4*)(C + (size_t)row * N + colb) =
                    make_float4(acc[i][0], acc[i][1], acc[i][2], acc[i][3]);
            if (colb + 4 < N)
                *(float4*)(C + (size_t)row * N + colb + 4) =
                    make_float4(acc[i][4], acc[i][5], acc[i][6], acc[i][7]);
        }
    }

    if (STATS) {
        // pass 1: column sums
        float s[TN];
        #pragma unroll
        for (int j = 0; j < TN; j++) {
            s[j] = 0.f;
            #pragma unroll
            for (int i = 0; i < TM; i++) {
                int row = m0 + ty * TM + i;
                if (row < M) s[j] += acc[i][j];
            }
        }
        #pragma unroll
        for (int j = 0; j < TN; j++) red[ty][tx * TN + j] = s[j];
        __syncthreads();
        if (tid < BN) {
            float t = 0.f;
            #pragma unroll
            for (int r = 0; r < 16; r++) t += red[r][tid];
            int col = n0 + tid;
            if (col < N) atomicAdd(&sum_out[col], t);
        }
        __syncthreads();
        // pass 2: column sum of squares
        #pragma unroll
        for (int j = 0; j < TN; j++) {
            s[j] = 0.f;
            #pragma unroll
            for (int i = 0; i < TM; i++) {
                int row = m0 + ty * TM + i;
                if (row < M) s[j] = fmaf(acc[i][j], acc[i][j], s[j]);
            }
        }
        #pragma unroll
        for (int j = 0; j < TN; j++) red[ty][tx * TN + j] = s[j];
        __syncthreads();
        if (tid < BN) {
            float t = 0.f;
            #pragma unroll
            for (int r = 0; r < 16; r++) t += red[r][tid];
            int col = n0 + tid;
            if (col < N) atomicAdd(&sq_out[col], t);
        }
    }
}

// ---------------- BN finalize: a = g*rstd, c = beta - mean*a ----------------
__global__ void k_finalize(const float* __restrict__ sum, const float* __restrict__ sq,
                           const float* __restrict__ gam, const float* __restrict__ bet,
                           float* __restrict__ a, float* __restrict__ c, int n) {
    int i = blockIdx.x * blockDim.x + threadIdx.x;
    if (i < n) {
        float m   = sum[i] * (1.f / NN);
        float var = sq[i] * (1.f / NN) - m * m;
        float r   = rsqrtf(var + EPSV);
        float av  = gam[i] * r;
        a[i] = av;
        c[i] = bet[i] - m * av;
    }
}

// ---------------- final output: h = a2*hraw + c2 (no relu), pool by batch ----------------
__global__ void k_output(const int* __restrict__ batch,
                         float* __restrict__ out_h, float* __restrict__ out_pool) {
    int idx = blockIdx.x * blockDim.x + threadIdx.x;
    if (idx < NN * HID) {
        int n = idx / HID;
        int f = idx - n * HID;
        float v = fmaf(g_a2[f], g_hraw[idx], g_c2[f]);
        out_h[idx] = v;
        atomicAdd(&out_pool[(size_t)batch[n] * HID + f], v);
    }
}

// ---------------- host driver ----------------
extern "C" void kernel_launch(void* const* d_in, const int* in_sizes, int n_in,
                              void* d_out, int out_size) {
    const int*   batch = (const int*)  d_in[0];
    const float* x     = (const float*)d_in[1];
    const int*   ei    = (const int*)  d_in[2];   // [2, NE]: src then dst
    const float* ea    = (const float*)d_in[3];
    const float* linW  = (const float*)d_in[4];
    const float* linb  = (const float*)d_in[5];
    const float* W1s   = (const float*)d_in[6];
    const float* b1s   = (const float*)d_in[7];
    const float* g1s   = (const float*)d_in[8];
    const float* be1s  = (const float*)d_in[9];
    const float* W2s   = (const float*)d_in[10];
    const float* b2s   = (const float*)d_in[11];
    const float* gos   = (const float*)d_in[12];
    const float* bos   = (const float*)d_in[13];

    float* out      = (float*)d_out;
    float* out_h    = out;
    float* out_pool = out + (size_t)NN * HID;

    const int* src = ei;
    const int* dst = ei + NE;

    float *p_hraw, *p_agg, *p_t;
    float *p_sum1, *p_sq1, *p_a1, *p_c1, *p_sum2, *p_sq2, *p_a2, *p_c2;
    cudaGetSymbolAddress((void**)&p_hraw, g_hraw);
    cudaGetSymbolAddress((void**)&p_agg,  g_agg);
    cudaGetSymbolAddress((void**)&p_t,    g_t);
    cudaGetSymbolAddress((void**)&p_sum1, g_sum1);
    cudaGetSymbolAddress((void**)&p_sq1,  g_sq1);
    cudaGetSymbolAddress((void**)&p_a1,   g_a1);
    cudaGetSymbolAddress((void**)&p_c1,   g_c1);
    cudaGetSymbolAddress((void**)&p_sum2, g_sum2);
    cudaGetSymbolAddress((void**)&p_sq2,  g_sq2);
    cudaGetSymbolAddress((void**)&p_a2,   g_a2);
    cudaGetSymbolAddress((void**)&p_c2,   g_c2);

    const int EB = (NE + 255) / 256;

    // ---- CSR build ----
    k_zero_deg<<<(NN + 255) / 256, 256>>>();
    k_count<<<EB, 256>>>(dst);
    k_scan<<<1, 1024>>>();
    k_scatter<<<EB, 256>>>(src, dst, ea);

    // ---- h0 = x @ linW + linb ----
    {
        dim3 grid((HID + BN - 1) / BN, (NN + BM - 1) / BM);
        k_gemm<false, false><<<grid, 256>>>(x, linW, linb, nullptr, nullptr,
                                            p_hraw, NN, HID, 2 * 10, nullptr, nullptr);
    }

    dim3 grid1((HID2 + BN - 1) / BN, (NN + BM - 1) / BM);  // 5 x 391
    dim3 grid2((HID  + BN - 1) / BN, (NN + BM - 1) / BM);  // 3 x 391

    for (int i = 0; i < NLAYER; i++) {
        // message passing + segment sum (input transform = previous layer BN+relu)
        if (i == 0)
            k_spmm<false><<<NN, 320>>>(p_hraw, nullptr, nullptr);
        else
            k_spmm<true><<<NN, 320>>>(p_hraw, p_a2, p_c2);

        // GEMM1 + fused stats
        k_zero_f<<<(HID2 + 255) / 256, 256>>>(p_sum1, HID2);
        k_zero_f<<<(HID2 + 255) / 256, 256>>>(p_sq1, HID2);
        k_gemm<false, true><<<grid1, 256>>>(p_agg, W1s + (size_t)i * HID * HID2,
                                            b1s + (size_t)i * HID2, nullptr, nullptr,
                                            p_t, NN, HID2, HID, p_sum1, p_sq1);
        k_finalize<<<(HID2 + 255) / 256, 256>>>(p_sum1, p_sq1,
                                                g1s + (size_t)i * HID2, be1s + (size_t)i * HID2,
                                                p_a1, p_c1, HID2);

        // GEMM2 with fused relu(bn1) on A-load, + fused stats
        k_zero_f<<<(HID + 255) / 256, 256>>>(p_sum2, HID);
        k_zero_f<<<(HID + 255) / 256, 256>>>(p_sq2, HID);
        k_gemm<true, true><<<grid2, 256>>>(p_t, W2s + (size_t)i * HID2 * HID,
                                           b2s + (size_t)i * HID, p_a1, p_c1,
                                           p_hraw, NN, HID, HID2, p_sum2, p_sq2);
        k_finalize<<<(HID + 255) / 256, 256>>>(p_sum2, p_sq2,
                                               gos + (size_t)i * HID, bos + (size_t)i * HID,
                                               p_a2, p_c2, HID);
    }

    // ---- output: h (bn, no relu) and xpool ----
    k_zero_f<<<(NG * HID + 255) / 256, 256>>>(out_pool, NG * HID);
    k_output<<<((NN * HID) + 255) / 256, 256>>>(batch, out_h, out_pool);
}